// round 11
// baseline (speedup 1.0000x reference)
#include <cuda_runtime.h>
#include <cstdint>

// x: [64, 3, 512, 512] float32
// keep_mask: [64, 32, 32] -> widened to 32-bit words (nonzero == keep)
// out = x * upsample16(keep_mask)
//
// R11: FOUR warp-strided float4 slots per thread (block tile = 1024
// consecutive float4s = 16KB; slot stride = 256 float4s = 4KB).
//  - every LDG/STG: 32 lanes on consecutive float4s -> 4-line footprint
//  - 4 independent mask chains + 4 independently-predicated data loads
//    per thread -> read MLP doubled vs R10 (the proven winning axis)
//  - elision of masked-patch reads kept (~32MB saved)

static constexpr int B = 64;
static constexpr int C = 3;
static constexpr int H = 512;
static constexpr int W = 512;
static constexpr long long N  = (long long)B * C * H * W;  // 50,331,648 floats
static constexpr long long N4 = N / 4;                     // 12,582,912 float4s

static constexpr int THREADS = 256;
static constexpr int SLOTS   = 4;
// each block covers SLOTS*THREADS consecutive float4s
static constexpr long long BLOCKS = N4 / (SLOTS * THREADS); // 12288, exact

__device__ __forceinline__ bool mask_at(const uint32_t* __restrict__ keep,
                                        long long i /*float4 idx*/)
{
    long long base = i << 2;               // float index
    int w  = (int)(base & (W - 1));        // W = 512
    int h  = (int)((base >> 9) & (H - 1)); // H = 512
    int b  = (int)(base >> 18) / C;        // C = 3
    return __ldg(keep + b * 1024 + ((h >> 4) << 5) + (w >> 4)) != 0u;
}

__global__ void __launch_bounds__(THREADS) patchmask_kernel(
    const float4* __restrict__ x4,
    const uint32_t* __restrict__ keep,
    float4* __restrict__ out4)
{
    long long i0 = (long long)blockIdx.x * (SLOTS * THREADS) + threadIdx.x;

    bool m[SLOTS];
#pragma unroll
    for (int k = 0; k < SLOTS; k++)
        m[k] = mask_at(keep, i0 + (long long)k * THREADS);

    const float4 z = make_float4(0.f, 0.f, 0.f, 0.f);
    float4 v[SLOTS];
#pragma unroll
    for (int k = 0; k < SLOTS; k++)
        v[k] = m[k] ? __ldcs(x4 + i0 + (long long)k * THREADS) : z;

#pragma unroll
    for (int k = 0; k < SLOTS; k++)
        __stcs(out4 + i0 + (long long)k * THREADS, v[k]);
}

extern "C" void kernel_launch(void* const* d_in, const int* in_sizes, int n_in,
                              void* d_out, int out_size)
{
    const float4*   x4   = (const float4*)d_in[0];
    const uint32_t* keep = (const uint32_t*)d_in[1];
    float4*         out4 = (float4*)d_out;

    patchmask_kernel<<<(unsigned)BLOCKS, THREADS>>>(x4, keep, out4);
}